// round 14
// baseline (speedup 1.0000x reference)
#include <cuda_runtime.h>
#include <cstdint>

// LinearPositionInterpolation — segment-parallel, streaming float4 stores.
//   index: (n,) int32 sorted keypoints (n=129, uniform spacing 32 here)
//   value: (batch, n, dim) fp32   (32, 129, 256)
//   out:   (batch, m, dim) fp32, m = index[n-1]-index[0] = 4096
//
// Converged model: kernel is pinned at the LTS chip write cap (~6300 B/cyc,
// path-independent) — 134MB / 6.3TB/s ≈ 21.5us; all store routes tie.
// Champion config = __stcs + float4 + dense (seg,batch) grid. This round:
// BLOCK=512 (ROWS=8) to halve CTA count and amortize per-CTA setup over 2x
// stores; inner loop identical.

#define DIM    256
#define DIM4   (DIM / 4)          // 64 float4 columns per row
#define ROWS   8                  // row-groups per CTA
#define BLOCK  (ROWS * DIM4)      // 512 threads

__global__ __launch_bounds__(BLOCK)
void lpi_seg_kernel(const int* __restrict__ index,
                    const float4* __restrict__ value,
                    float4* __restrict__ out,
                    int n, int m)
{
    const int s  = blockIdx.x;                 // segment 0..n-2
    const int b  = blockIdx.y;                 // batch
    const int d  = threadIdx.x & (DIM4 - 1);   // float4 column
    const int rg = threadIdx.x >> 6;           // row-group 0..ROWS-1

    const int base = __ldg(&index[0]);
    const int x0   = __ldg(&index[s])     - base;
    const int x1   = __ldg(&index[s + 1]) - base;
    const int L    = x1 - x0;
    const float invL = 1.0f / (float)L;

    // 32-bit element offsets (out: 8.4M float4 elements < 2^31).
    const int vrow = (b * n + s) * DIM4 + d;
    const float4 y0 = value[vrow];
    const float4 y1 = value[vrow + DIM4];
    const float4 dy = make_float4(y1.x - y0.x, y1.y - y0.y,
                                  y1.z - y0.z, y1.w - y0.w);

    float4* orow = out + ((b * m + x0 + rg) * DIM4 + d);
    const int ostep = ROWS * DIM4;

    float w = (float)(rg + 1) * invL;
    const float wstep = (float)ROWS * invL;

    if (L == 32) {
        // Fast path: 4 iterations fully unrolled, streaming stores.
        #pragma unroll
        for (int it = 0; it < 32 / ROWS; ++it) {
            float4 o;
            o.x = fmaf(dy.x, w, y0.x);
            o.y = fmaf(dy.y, w, y0.y);
            o.z = fmaf(dy.z, w, y0.z);
            o.w = fmaf(dy.w, w, y0.w);
            __stcs(orow, o);
            orow += ostep;
            w += wstep;
        }
    } else {
        for (int p = x0 + 1 + rg; p <= x1; p += ROWS) {
            float4 o;
            o.x = fmaf(dy.x, w, y0.x);
            o.y = fmaf(dy.y, w, y0.y);
            o.z = fmaf(dy.z, w, y0.z);
            o.w = fmaf(dy.w, w, y0.w);
            __stcs(orow, o);
            orow += ostep;
            w += wstep;
        }
    }
}

extern "C" void kernel_launch(void* const* d_in, const int* in_sizes, int n_in,
                              void* d_out, int out_size)
{
    const int*   index = (const int*)d_in[0];
    const float* value = (const float*)d_in[1];
    float*       outp  = (float*)d_out;

    int n = in_sizes[0];                                   // 129
    long long velems = in_sizes[1];
    int batch = (int)(velems / ((long long)n * DIM));      // 32
    int m = (int)((long long)out_size / ((long long)batch * DIM)); // 4096

    dim3 grid(n - 1, batch);             // (128, 32) = 4096 CTAs... wait: 2048? no — (n-1)=128, batch=32 => 4096? CTA count halves only if rows split differently; grid unchanged, block doubled covers same rows in half the iterations.
    dim3 block(BLOCK);                   // 512 threads

    lpi_seg_kernel<<<grid, block>>>(index,
                                    (const float4*)value,
                                    (float4*)outp,
                                    n, m);
}

// round 16
// speedup vs baseline: 1.0222x; 1.0222x over previous
#include <cuda_runtime.h>
#include <cstdint>

// LinearPositionInterpolation — FINAL: segment-parallel streaming float4.
//   index: (n,) int32 sorted keypoints (n=129, uniform spacing 32 here)
//   value: (batch, n, dim) fp32   (32, 129, 256)
//   out:   (batch, m, dim) fp32, m = index[n-1]-index[0] = 4096
//
// Converged across 10 structural variants: kernel is pinned at the LTS chip
// write cap (~6300 B/cyc, path-independent) => 134MB / 6.3TB/s ≈ 21.5us
// floor. Champion end-to-end config (bench 23.0us, reproduced): __stcs
// streaming stores, float4, ROWS=4 (256 threads), dense (segment,batch)
// grid, 32-bit element addressing, loop-incremental w, unrolled L==32 path.

#define DIM    256
#define DIM4   (DIM / 4)          // 64 float4 columns per row
#define ROWS   4                  // row-groups per CTA
#define BLOCK  (ROWS * DIM4)      // 256 threads

__global__ __launch_bounds__(BLOCK)
void lpi_seg_kernel(const int* __restrict__ index,
                    const float4* __restrict__ value,
                    float4* __restrict__ out,
                    int n, int m)
{
    const int s  = blockIdx.x;                 // segment 0..n-2
    const int b  = blockIdx.y;                 // batch
    const int d  = threadIdx.x & (DIM4 - 1);   // float4 column
    const int rg = threadIdx.x >> 6;           // row-group 0..ROWS-1

    const int base = __ldg(&index[0]);
    const int x0   = __ldg(&index[s])     - base;
    const int x1   = __ldg(&index[s + 1]) - base;
    const int L    = x1 - x0;
    const float invL = 1.0f / (float)L;

    // 32-bit element offsets (out: 8.4M float4 elements < 2^31).
    const int vrow = (b * n + s) * DIM4 + d;
    const float4 y0 = value[vrow];
    const float4 y1 = value[vrow + DIM4];
    const float4 dy = make_float4(y1.x - y0.x, y1.y - y0.y,
                                  y1.z - y0.z, y1.w - y0.w);

    float4* orow = out + ((b * m + x0 + rg) * DIM4 + d);
    const int ostep = ROWS * DIM4;

    // w for row-group rg starts at (rg+1)*invL and advances ROWS*invL.
    float w = (float)(rg + 1) * invL;
    const float wstep = (float)ROWS * invL;

    if (L == 32) {
        // Fast path: 8 iterations fully unrolled, streaming stores.
        #pragma unroll
        for (int it = 0; it < 32 / ROWS; ++it) {
            float4 o;
            o.x = fmaf(dy.x, w, y0.x);
            o.y = fmaf(dy.y, w, y0.y);
            o.z = fmaf(dy.z, w, y0.z);
            o.w = fmaf(dy.w, w, y0.w);
            __stcs(orow, o);
            orow += ostep;
            w += wstep;
        }
    } else {
        for (int p = x0 + 1 + rg; p <= x1; p += ROWS) {
            float4 o;
            o.x = fmaf(dy.x, w, y0.x);
            o.y = fmaf(dy.y, w, y0.y);
            o.z = fmaf(dy.z, w, y0.z);
            o.w = fmaf(dy.w, w, y0.w);
            __stcs(orow, o);
            orow += ostep;
            w += wstep;
        }
    }
}

extern "C" void kernel_launch(void* const* d_in, const int* in_sizes, int n_in,
                              void* d_out, int out_size)
{
    const int*   index = (const int*)d_in[0];
    const float* value = (const float*)d_in[1];
    float*       outp  = (float*)d_out;

    int n = in_sizes[0];                                   // 129
    long long velems = in_sizes[1];
    int batch = (int)(velems / ((long long)n * DIM));      // 32
    int m = (int)((long long)out_size / ((long long)batch * DIM)); // 4096

    dim3 grid(n - 1, batch);             // (128, 32) = 4096 CTAs
    dim3 block(BLOCK);                   // 256 threads

    lpi_seg_kernel<<<grid, block>>>(index,
                                    (const float4*)value,
                                    (float4*)outp,
                                    n, m);
}